// round 17
// baseline (speedup 1.0000x reference)
#include <cuda_runtime.h>

// CoincidenceLIFBank: B=32 x T=4096 x D=256.
// Output: [0,B*D) pooled | [B*D,+B*D*T) spikes | +D rw | +D tw | +D beta
//
// NUMERICS FROZEN (rel_err 9.894e-4 across R6-R16):
//   rw/tw = max(x,0) + logf(1 + expf(-|x|));  sigmoid = 1/(1+expf(-x))
//   beta  = fadd(0.7, fmul(0.295, sigmoid))         (uncontracted)
//   cur   = fadd(fmul(rw, rv), fmul(tw, tv))        (UNcontracted)
//   mp    = fma(beta, m, cur); ms = fadd(mp,-1); p = (mp>=1)
//   m = p ? ms : mp;  s = p ? 1 : 0
// OOB ref reads exact 0.0f from the zero-padded smem row. cnt regrouping is
// exact (integer-valued floats).
//
// R17: SMSP spreading. Previous rounds ran 256 single-warp blocks -> every
// warp was wid0 -> SMSP0; 108 SMs held TWO warps on one scheduler (measured
// 23-25 cyc/step == two 12.5-issue warps sharing 1 issue/cyc). Now: 64
// blocks x 128 threads, warp w owns delay-group w -> SMSPs 0..3 each get
// exactly one warp. Hot loop is byte-identical to R16. sref/stgt staged once
// per block (4 warps share).

#define NB 32
#define NT 4096
#define ND 256
#define THRESH 1.0f
#define TILE 128
#define TSTRIDE 132          // tile row stride in floats (528B, 16B-aligned)
#define SREF_N (NT + 256)    // zero pad: delay<128 + 24-step prefetch slack

#define OFF_SREF 0
#define OFF_STGT SREF_N
#define OFF_TILE (SREF_N + NT)
#define TILE_FLOATS (32 * TSTRIDE)
#define SMEM_FLOATS (OFF_TILE + 4 * TILE_FLOATS)
#define SMEM_BYTES (SMEM_FLOATS * 4)     // 101,376 B

__device__ __forceinline__ float softplus_xla(float x) {
    const float u = expf(-fabsf(x));
    return __fadd_rn(fmaxf(x, 0.0f), logf(__fadd_rn(1.0f, u)));
}
__device__ __forceinline__ float sigmoid_xla(float x) {
    return 1.0f / (__fadd_rn(1.0f, expf(-x)));
}

// load tv/rv for a 4-step group (identical to R12/R16)
__device__ __forceinline__ void fetch4(const float* __restrict__ sref,
                                       const float* __restrict__ stgt,
                                       const int delay, const int t,
                                       float* __restrict__ rv,
                                       float* __restrict__ tv)
{
    const float4 v = *(const float4*)(stgt + (t & (NT - 1)));
    tv[0] = v.x; tv[1] = v.y; tv[2] = v.z; tv[3] = v.w;
#pragma unroll
    for (int j = 0; j < 4; j++) rv[j] = sref[delay + t + j];
}

// 4 serial LIF steps (identical arithmetic to R16)
__device__ __forceinline__ void lif4(const float rw, const float tw,
                                     const float beta,
                                     const float* __restrict__ rv,
                                     const float* __restrict__ tv,
                                     float& m, float& cnt,
                                     float* __restrict__ sp)
{
#pragma unroll
    for (int j = 0; j < 4; j++) {
        const float cur = __fadd_rn(__fmul_rn(rw, rv[j]), __fmul_rn(tw, tv[j]));
        const float mp  = __fmaf_rn(beta, m, cur);
        const float ms  = __fadd_rn(mp, -THRESH);
        const bool  p   = (mp >= THRESH);
        m = p ? ms : mp;
        sp[j] = p ? 1.0f : 0.0f;
    }
    cnt += __fadd_rn(__fadd_rn(sp[0], sp[1]), __fadd_rn(sp[2], sp[3]));
}

__global__ void __launch_bounds__(128)
lif_bank_kernel(const float* __restrict__ ref,
                const float* __restrict__ tgt,
                const int*   __restrict__ delays,
                const float* __restrict__ rw_raw,
                const float* __restrict__ tw_raw,
                const float* __restrict__ beta_raw,
                float* __restrict__ out)
{
    extern __shared__ float smem[];
    float* __restrict__ sref = smem + OFF_SREF;
    float* __restrict__ stgt = smem + OFF_STGT;

    // 64 blocks x 4 warps: block -> (b, half); warp w -> 32-delay group.
    const int tid  = threadIdx.x;
    const int wid  = tid >> 5;            // 0..3 -> SMSP 0..3
    const int lane = tid & 31;
    const int b    = blockIdx.x >> 1;     // 32 batches
    const int half = blockIdx.x & 1;      // d range halves
    const int d0   = half * 128 + wid * 32;
    const int d    = d0 + lane;

    float* __restrict__ stile = smem + OFF_TILE + wid * TILE_FLOATS;

    // ---- stage ref + tgt once per block (cooperative, coalesced) ----
    {
        const float4* __restrict__ ref4 = (const float4*)(ref + b * NT);
        const float4* __restrict__ tgt4 = (const float4*)(tgt + b * NT);
        float4* sr4 = (float4*)sref;
        float4* st4 = (float4*)stgt;
#pragma unroll
        for (int i = 0; i < NT / 4 / 128; i++) {        // 8 iters
            sr4[tid + 128 * i] = __ldg(ref4 + tid + 128 * i);
            st4[tid + 128 * i] = __ldg(tgt4 + tid + 128 * i);
        }
        if (tid < (SREF_N - NT) / 4)                    // zero pad (64 float4)
            sr4[NT / 4 + tid] = make_float4(0.f, 0.f, 0.f, 0.f);
    }

    // ---- per-bank params (frozen recipe) ----
    const float rw   = softplus_xla(rw_raw[d]);
    const float tw   = softplus_xla(tw_raw[d]);
    const float beta = __fadd_rn(0.7f, __fmul_rn(0.295f, sigmoid_xla(beta_raw[d])));
    const int   delay = delays[d];

    float* out_pooled = out;
    float* out_spk    = out + NB * ND;
    float* out_rw     = out + NB * ND + (size_t)NB * ND * NT;
    float* out_tw     = out_rw + ND;
    float* out_beta   = out_tw + ND;

    float m = 0.0f;
    float cnt = 0.0f;

    __syncthreads();   // staged rows visible block-wide (only block sync)

    // ---- 4-buffer rotating pipeline, prefetch distance 2 (as R16) ----
    float tvA[4], rvA[4], tvB[4], rvB[4];
    float tvC[4], rvC[4], tvD[4], rvD[4];
    float sp[4];
    fetch4(sref, stgt, delay, 0, rvA, tvA);
    fetch4(sref, stgt, delay, 4, rvB, tvB);

    for (int tile0 = 0; tile0 < NT; tile0 += TILE) {
#pragma unroll 2
        for (int t0 = tile0; t0 < tile0 + TILE; t0 += 16) {
            const int o = t0 - tile0;

            fetch4(sref, stgt, delay, t0 + 8, rvC, tvC);
            lif4(rw, tw, beta, rvA, tvA, m, cnt, sp);
            *(float4*)&stile[lane * TSTRIDE + o] =
                make_float4(sp[0], sp[1], sp[2], sp[3]);

            fetch4(sref, stgt, delay, t0 + 12, rvD, tvD);
            lif4(rw, tw, beta, rvB, tvB, m, cnt, sp);
            *(float4*)&stile[lane * TSTRIDE + o + 4] =
                make_float4(sp[0], sp[1], sp[2], sp[3]);

            fetch4(sref, stgt, delay, t0 + 16, rvA, tvA);
            lif4(rw, tw, beta, rvC, tvC, m, cnt, sp);
            *(float4*)&stile[lane * TSTRIDE + o + 8] =
                make_float4(sp[0], sp[1], sp[2], sp[3]);

            fetch4(sref, stgt, delay, t0 + 20, rvB, tvB);
            lif4(rw, tw, beta, rvD, tvD, m, cnt, sp);
            *(float4*)&stile[lane * TSTRIDE + o + 12] =
                make_float4(sp[0], sp[1], sp[2], sp[3]);
        }
        __syncwarp();   // private tile: warp-local handoff only

        // ---- dump: 32 rows x 512B contiguous STG.128 bursts ----
#pragma unroll 4
        for (int r = 0; r < 32; r++) {
            const float4 w = *(const float4*)&stile[r * TSTRIDE + lane * 4];
            float* dst = out_spk + (size_t)(b * ND + d0 + r) * NT + tile0;
            *(float4*)(dst + lane * 4) = w;
        }
        __syncwarp();
    }

    out_pooled[b * ND + d] = cnt * (1.0f / NT);

    if (b == 0) {   // blocks 0,1 cover d = 0..255 exactly once
        out_rw[d]   = rw;
        out_tw[d]   = tw;
        out_beta[d] = beta;
    }
}

extern "C" void kernel_launch(void* const* d_in, const int* in_sizes, int n_in,
                              void* d_out, int out_size)
{
    const float* ref      = (const float*)d_in[0];
    const float* tgt      = (const float*)d_in[1];
    const int*   delays   = (const int*)  d_in[2];
    const float* rw_raw   = (const float*)d_in[3];
    const float* tw_raw   = (const float*)d_in[4];
    const float* beta_raw = (const float*)d_in[5];
    float* out = (float*)d_out;

    cudaFuncSetAttribute(lif_bank_kernel,
                         cudaFuncAttributeMaxDynamicSharedMemorySize,
                         SMEM_BYTES);

    // 64 blocks x 128 threads: 1 block/SM, warp w -> SMSP w (no scheduler
    // sharing). Hot loop identical to R16.
    lif_bank_kernel<<<NB * 2, 128, SMEM_BYTES>>>(ref, tgt, delays, rw_raw,
                                                 tw_raw, beta_raw, out);
}